// round 15
// baseline (speedup 1.0000x reference)
#include <cuda_runtime.h>
#include <cuda_fp16.h>
#include <cstdint>
#include <float.h>

// ---------------------------------------------------------------------------
// Problem constants
// ---------------------------------------------------------------------------
#define B_     4
#define S_     2048
#define DIN    1024
#define DINNER 1024
#define DOUT   1024
#define M1     (B_ * S_)        // 8192
#define N1     (3 * DINNER)     // 3072

// GEMM tile config (mma.sync)
#define BM 128
#define BN 128
#define BK 64
#define NTH 256                 // 8 warps: 4 (m) x 2 (n)
#define PAD 8
#define LDSROW (BK + PAD)       // 72 fp16 per smem row (144 B)
#define TILE_B (BM * LDSROW * 2)    // 18432 bytes per tile
#define STAGE_B (2 * TILE_B)        // A, B = 36864
#define NSTAGE 3
#define SMEM_TOTAL (NSTAGE * STAGE_B)   // 110592 (108 KB) -> 2 CTAs/SM

// ---------------------------------------------------------------------------
// PTX helpers (baseline-PTX legal on compute_103)
// ---------------------------------------------------------------------------
__device__ __forceinline__ uint32_t smem_u32(const void* p) {
    uint32_t a;
    asm("{ .reg .u64 t; cvta.to.shared.u64 t, %1; cvt.u32.u64 %0, t; }"
        : "=r"(a) : "l"(p));
    return a;
}

__device__ __forceinline__ void cp_async16(uint32_t dst, const void* src) {
    asm volatile("cp.async.cg.shared.global [%0], [%1], 16;"
                 :: "r"(dst), "l"(src));
}
#define CP_COMMIT() asm volatile("cp.async.commit_group;" ::: "memory")
#define CP_WAIT(n)  asm volatile("cp.async.wait_group %0;" :: "n"(n) : "memory")

__device__ __forceinline__ void ldmat_x4(uint32_t& r0, uint32_t& r1,
                                         uint32_t& r2, uint32_t& r3,
                                         uint32_t addr) {
    asm volatile("ldmatrix.sync.aligned.m8n8.x4.shared.b16 {%0,%1,%2,%3}, [%4];"
                 : "=r"(r0), "=r"(r1), "=r"(r2), "=r"(r3) : "r"(addr));
}

__device__ __forceinline__ void mma_fp16(float* c, const uint32_t* a,
                                         uint32_t b0, uint32_t b1) {
    asm volatile(
        "mma.sync.aligned.m16n8k16.row.col.f32.f16.f16.f32 "
        "{%0,%1,%2,%3}, {%4,%5,%6,%7}, {%8,%9}, {%0,%1,%2,%3};"
        : "+f"(c[0]), "+f"(c[1]), "+f"(c[2]), "+f"(c[3])
        : "r"(a[0]), "r"(a[1]), "r"(a[2]), "r"(a[3]), "r"(b0), "r"(b1));
}

// ---------------------------------------------------------------------------
// Scratch (static device globals)
// ---------------------------------------------------------------------------
__device__ float g_sim[(size_t)B_ * S_ * S_];            // 64 MB fp32

__device__ __half g_xh[(size_t)M1 * DIN];                // 16 MB
__device__ __half g_wqkvt[(size_t)N1 * DIN];             // 6 MB (transposed)
__device__ __half g_woutt[(size_t)DOUT * DINNER];        // 2 MB (transposed)
__device__ __half g_qkvh[(size_t)M1 * N1];               // 48 MB
__device__ __half g_vt[(size_t)B_ * DINNER * S_];        // 16 MB (V^T per batch)
__device__ __half g_attn[(size_t)B_ * S_ * S_];          // 32 MB
__device__ __half g_inner[(size_t)M1 * DINNER];          // 16 MB

// ---------------------------------------------------------------------------
// Conversion kernels
// ---------------------------------------------------------------------------
__global__ void cvt_rm_kernel(const float4* __restrict__ src,
                              __half2* __restrict__ h, long long n4) {
    long long i = (long long)blockIdx.x * blockDim.x + threadIdx.x;
    long long stride = (long long)gridDim.x * blockDim.x;
    for (; i < n4; i += stride) {
        float4 v = src[i];
        h[2 * i]     = __floats2half2_rn(v.x, v.y);
        h[2 * i + 1] = __floats2half2_rn(v.z, v.w);
    }
}

// fp32 [R,C] (row stride sld) -> transposed fp16 [C,R] (row stride dld)
__global__ void cvt_tr_kernel(const float* __restrict__ src,
                              __half* __restrict__ h,
                              int sld, int dld,
                              long long sbatch, long long dbatch) {
    __shared__ float t[32][33];
    const int c0 = blockIdx.x * 32;
    const int r0 = blockIdx.y * 32;
    const long long sb = (long long)blockIdx.z * sbatch;
    const long long db = (long long)blockIdx.z * dbatch;
    const int tx = threadIdx.x, ty = threadIdx.y;

    #pragma unroll
    for (int i = 0; i < 32; i += 8)
        t[ty + i][tx] = src[sb + (long long)(r0 + ty + i) * sld + c0 + tx];
    __syncthreads();
    #pragma unroll
    for (int i = 0; i < 32; i += 8) {
        long long o = db + (long long)(c0 + ty + i) * dld + r0 + tx;
        h[o] = __float2half(t[tx][ty + i]);
    }
}

// fp16 [R,C] (row stride sld) -> transposed fp16 [C,R] (row stride dld)
__global__ void cvt_tr_half_kernel(const __half* __restrict__ src,
                                   __half* __restrict__ h,
                                   int sld, int dld,
                                   long long sbatch, long long dbatch) {
    __shared__ __half t[32][33];
    const int c0 = blockIdx.x * 32;
    const int r0 = blockIdx.y * 32;
    const long long sb = (long long)blockIdx.z * sbatch;
    const long long db = (long long)blockIdx.z * dbatch;
    const int tx = threadIdx.x, ty = threadIdx.y;

    #pragma unroll
    for (int i = 0; i < 32; i += 8)
        t[ty + i][tx] = src[sb + (long long)(r0 + ty + i) * sld + c0 + tx];
    __syncthreads();
    #pragma unroll
    for (int i = 0; i < 32; i += 8) {
        long long o = db + (long long)(c0 + ty + i) * dld + r0 + tx;
        h[o] = t[tx][ty + i];
    }
}

// ---------------------------------------------------------------------------
// mma.sync fp16 GEMM: C[M,N] = scale * sum_k A[m,k]*B[n,k] (+bias)
// A: [M,K] K-contiguous ; B: [N,K] K-contiguous
// BK=64, 3-stage cp.async ring, 1 barrier/chunk, software-pipelined fragments,
// prefetch cp.asyncs spread across the 8 MMA phases with strength-reduced
// incremental addressing.
// ---------------------------------------------------------------------------
struct GemmArgs {
    const __half *A, *B;
    float* C;                    // nullable fp32 out
    __half* Ch;                  // nullable fp16 out
    const float* bias;           // nullable
    int K, lda, ldb, ldc;
    long long strideA, strideB, strideC;
    float scale;
    int causal_skip;             // skip CTA if bx > by
    int kmax_mode;               // K_eff = min(K, (by+1)*BM)
};

__device__ __forceinline__ void load_tile(const __half* __restrict__ g,
                                          int row0, int ld, int k0, uint32_t sm) {
    const int tid = threadIdx.x;
    #pragma unroll
    for (int t = 0; t < 4; t++) {
        int idx = t * NTH + tid;        // 0..1023
        int r  = idx >> 3;              // 0..127
        int kc = (idx & 7) * 8;         // 0..56
        cp_async16(sm + (uint32_t)(r * LDSROW + kc) * 2,
                   g + (long long)(row0 + r) * ld + k0 + kc);
    }
}

__global__ void __launch_bounds__(NTH, 2)
gemm_mma_kernel(GemmArgs args)
{
    const int bx = blockIdx.x, by = blockIdx.y, bb = blockIdx.z;
    if (args.causal_skip && bx > by) return;

    extern __shared__ char smem[];
    const uint32_t smem_base = smem_u32(smem);

    const int tid = threadIdx.x;
    const int wid = tid >> 5;
    const int lane = tid & 31;
    const int wm = wid >> 1;            // 0..3  (32-row slab)
    const int wn = wid & 1;             // 0..1  (64-col slab)
    const int lrow = lane & 15;         // ldmatrix row select
    const int lcol = (lane >> 4) * 8;   // ldmatrix k-half select

    const int lda = args.lda, ldb = args.ldb;
    const __half* A = args.A + (long long)bb * args.strideA;
    const __half* B = args.B + (long long)bb * args.strideB;

    const int Keff = args.kmax_mode ? min(args.K, (by + 1) * BM) : args.K;
    const int nch = Keff / BK;
    const int arow = by * BM;
    const int brow = bx * BN;

    float acc[2][8][4];
    #pragma unroll
    for (int i = 0; i < 2; i++)
        #pragma unroll
        for (int j = 0; j < 8; j++)
            #pragma unroll
            for (int k = 0; k < 4; k++) acc[i][j][k] = 0.f;

    // prologue: chunks 0,1 -> stages 0,1
    load_tile(A, arow, lda, 0, smem_base);
    load_tile(B, brow, ldb, 0, smem_base + TILE_B);
    CP_COMMIT();
    if (nch > 1) {
        load_tile(A, arow, lda, BK, smem_base + STAGE_B);
        load_tile(B, brow, ldb, BK, smem_base + STAGE_B + TILE_B);
        CP_COMMIT();
    }

    // --- strength-reduced prefetch addressing (per thread, loop-carried) ---
    const int tr  = tid >> 3;           // slice row 0..31
    const int tkc = (tid & 7) * 8;      // k offset within chunk
    const __half* pfA = A + (long long)(arow + tr) * lda + tkc + 2 * BK;
    const __half* pfB = B + (long long)(brow + tr) * ldb + tkc + 2 * BK;
    const long long lda32 = 32LL * lda;
    const long long ldb32 = 32LL * ldb;
    const uint32_t sdst = (uint32_t)(tr * LDSROW + tkc) * 2;

    // per-warp smem base offsets (loop-invariant)
    const uint32_t a_off0 = (uint32_t)((wm * 32 + lrow) * LDSROW) * 2 + lcol * 2;
    const uint32_t b_off0 = (uint32_t)((wn * 64 + lrow) * LDSROW) * 2 + lcol * 2;

    for (int c = 0; c < nch; c++) {
        // chunk c resident (1 group may stay in flight mid-stream)
        if (c < nch - 1) { CP_WAIT(1); } else { CP_WAIT(0); }
        __syncthreads();     // publish chunk c; stage (c+2)%3 free for overwrite

        const bool pf = (c + 2 < nch);
        const uint32_t sqpf = smem_base + ((c + 2) % NSTAGE) * STAGE_B;

        const uint32_t sp = smem_base + (c % NSTAGE) * STAGE_B;
        const uint32_t a_base = sp + a_off0;
        const uint32_t b_base = sp + TILE_B + b_off0;

        // ---- software-pipelined 8 phases: (kk 0..3) x (jg 0..1) ----
        uint32_t Abuf[2][8];   // [buf][mi*4 + r]
        uint32_t Bbuf[2][8];   // [buf][b0 x4, b1 x4]

        // preload phase 0 fragments: A(kk=0), B(kk=0, jg=0)
        {
            ldmat_x4(Abuf[0][0], Abuf[0][1], Abuf[0][2], Abuf[0][3], a_base);
            ldmat_x4(Abuf[0][4], Abuf[0][5], Abuf[0][6], Abuf[0][7],
                     a_base + (uint32_t)(16 * LDSROW) * 2);
            #pragma unroll
            for (int np = 0; np < 2; np++) {
                uint32_t r0, r1, r2, r3;
                ldmat_x4(r0, r1, r2, r3,
                         b_base + (uint32_t)(np * 16 * LDSROW) * 2);
                Bbuf[0][np * 2]     = r0; Bbuf[0][4 + np * 2]     = r2;
                Bbuf[0][np * 2 + 1] = r1; Bbuf[0][4 + np * 2 + 1] = r3;
            }
        }

        #pragma unroll
        for (int ph = 0; ph < 8; ph++) {
            const int jg = ph & 1;
            const int kk = ph >> 1;
            const int ab = kk & 1;
            const int bbuf = ph & 1;

            // one slice of the chunk-(c+2) gmem prefetch per phase
            // (addresses: loop-carried base + compile-time-constant offsets)
            if (pf) {
                if (ph < 4)
                    cp_async16(sqpf + sdst + (uint32_t)(ph * 32 * LDSROW * 2),
                               pfA + (long long)ph * lda32);
                else
                    cp_async16(sqpf + TILE_B + sdst
                                   + (uint32_t)((ph - 4) * 32 * LDSROW * 2),
                               pfB + (long long)(ph - 4) * ldb32);
            }

            // prefetch next phase's fragments
            if (ph < 7) {
                const int nkk = (ph + 1) >> 1;
                const int njg = (ph + 1) & 1;
                const uint32_t nkoff = (uint32_t)(nkk * 16) * 2;
                if (njg == 0) {   // new kk: load A(nkk)
                    const int nab = nkk & 1;
                    ldmat_x4(Abuf[nab][0], Abuf[nab][1], Abuf[nab][2], Abuf[nab][3],
                             a_base + nkoff);
                    ldmat_x4(Abuf[nab][4], Abuf[nab][5], Abuf[nab][6], Abuf[nab][7],
                             a_base + (uint32_t)(16 * LDSROW) * 2 + nkoff);
                }
                const int nbb = (ph + 1) & 1;
                #pragma unroll
                for (int np = 0; np < 2; np++) {
                    uint32_t r0, r1, r2, r3;
                    ldmat_x4(r0, r1, r2, r3,
                             b_base + (uint32_t)((njg * 2 + np) * 16 * LDSROW) * 2
                                    + nkoff);
                    Bbuf[nbb][np * 2]     = r0; Bbuf[nbb][4 + np * 2]     = r2;
                    Bbuf[nbb][np * 2 + 1] = r1; Bbuf[nbb][4 + np * 2 + 1] = r3;
                }
            }

            // 8 MMAs for this phase
            #pragma unroll
            for (int mi = 0; mi < 2; mi++)
                #pragma unroll
                for (int jl = 0; jl < 4; jl++)
                    mma_fp16(acc[mi][jg * 4 + jl], &Abuf[ab][mi * 4],
                             Bbuf[bbuf][jl], Bbuf[bbuf][4 + jl]);
        }

        if (pf) CP_COMMIT();
        pfA += BK;
        pfB += BK;
    }

    // epilogue (acc is thread-private; no sync needed)
    float* C = args.C ? args.C + (long long)bb * args.strideC : nullptr;
    __half* Ch = args.Ch ? args.Ch + (long long)bb * args.strideC : nullptr;
    const int g = lane >> 2;
    const int tig = lane & 3;

    #pragma unroll
    for (int mi = 0; mi < 2; mi++) {
        #pragma unroll
        for (int j = 0; j < 8; j++) {
            const int row0 = arow + wm * 32 + mi * 16 + g;
            const int col0 = brow + wn * 64 + j * 8 + 2 * tig;
            float v[4];
            #pragma unroll
            for (int k = 0; k < 4; k++) v[k] = acc[mi][j][k] * args.scale;
            if (args.bias) {
                v[0] += args.bias[col0];     v[1] += args.bias[col0 + 1];
                v[2] += args.bias[col0];     v[3] += args.bias[col0 + 1];
            }
            const long long o0 = (long long)row0 * args.ldc + col0;
            const long long o1 = (long long)(row0 + 8) * args.ldc + col0;
            if (C) {
                C[o0] = v[0]; C[o0 + 1] = v[1];
                C[o1] = v[2]; C[o1 + 1] = v[3];
            }
            if (Ch) {
                *(__half2*)(Ch + o0) = __floats2half2_rn(v[0], v[1]);
                *(__half2*)(Ch + o1) = __floats2half2_rn(v[2], v[3]);
            }
        }
    }
}

// ---------------------------------------------------------------------------
// Causal row softmax: fp32 sim -> fp16 probs, single-expf, zero-fill to 128
// ---------------------------------------------------------------------------
__global__ void __launch_bounds__(256)
softmax_kernel(const float* __restrict__ sim, __half* __restrict__ ph)
{
    const int i = blockIdx.x;
    const int b = blockIdx.y;
    const float* row = sim + ((size_t)b * S_ + i) * S_;
    __half* rh = ph + ((size_t)b * S_ + i) * S_;
    const int n = i + 1;

    __shared__ float red[256];
    const int t = threadIdx.x;

    float m = -FLT_MAX;
    #pragma unroll
    for (int it = 0; it < 8; it++) {
        int j = t + it * 256;
        if (j < n) m = fmaxf(m, row[j]);
    }
    red[t] = m; __syncthreads();
    for (int s = 128; s > 0; s >>= 1) {
        if (t < s) red[t] = fmaxf(red[t], red[t + s]);
        __syncthreads();
    }
    m = red[0]; __syncthreads();

    float ev[8];
    float sum = 0.f;
    #pragma unroll
    for (int it = 0; it < 8; it++) {
        int j = t + it * 256;
        float e = 0.f;
        if (j < n) e = expf(row[j] - m);
        ev[it] = e;
        sum += e;
    }
    red[t] = sum; __syncthreads();
    for (int s = 128; s > 0; s >>= 1) {
        if (t < s) red[t] += red[t + s];
        __syncthreads();
    }
    const float inv = 1.f / red[0];

    #pragma unroll
    for (int it = 0; it < 8; it++) {
        int j = t + it * 256;
        if (j < n) rh[j] = __float2half(ev[it] * inv);
    }
    const int pad_end = min(S_, ((n + 127) / 128) * 128);
    for (int j = n + t; j < pad_end; j += 256)
        rh[j] = __float2half(0.f);
}

// ---------------------------------------------------------------------------
// Launch
// ---------------------------------------------------------------------------
static void* sym(const void* s) { void* p; cudaGetSymbolAddress(&p, s); return p; }

extern "C" void kernel_launch(void* const* d_in, const int* in_sizes, int n_in,
                              void* d_out, int out_size)
{
    const float* x     = (const float*)d_in[0];
    const float* w_qkv = (const float*)d_in[1];
    const float* w_out = (const float*)d_in[2];
    const float* b_out = (const float*)d_in[3];
    float* out = (float*)d_out;

    float* simP = (float*)sym(g_sim);
    __half* xh    = (__half*)sym(g_xh);
    __half* wqt   = (__half*)sym(g_wqkvt);
    __half* wot   = (__half*)sym(g_woutt);
    __half* qkvh  = (__half*)sym(g_qkvh);
    __half* vt    = (__half*)sym(g_vt);
    __half* attn  = (__half*)sym(g_attn);
    __half* inner = (__half*)sym(g_inner);

    cudaFuncSetAttribute(gemm_mma_kernel,
                         cudaFuncAttributeMaxDynamicSharedMemorySize, SMEM_TOTAL);

    const float scale = 1.0f / 32.0f;   // DIM_INNER^-0.5

    // 1) input conversion / weight transposes
    cvt_rm_kernel<<<2048, 256>>>((const float4*)x, (__half2*)xh,
                                 (long long)M1 * DIN / 4);
    cvt_tr_kernel<<<dim3(N1 / 32, DIN / 32, 1), dim3(32, 8)>>>(
        w_qkv, wqt, N1, DIN, 0, 0);
    cvt_tr_kernel<<<dim3(DOUT / 32, DINNER / 32, 1), dim3(32, 8)>>>(
        w_out, wot, DOUT, DINNER, 0, 0);

    // 2) QKV projection -> fp16 qkvh only
    {
        GemmArgs a = { xh, wqt, nullptr, qkvh, nullptr,
                       DIN, DIN, DIN, N1, 0, 0, 0, 1.0f, 0, 0 };
        gemm_mma_kernel<<<dim3(N1 / BN, M1 / BM, 1), NTH, SMEM_TOTAL>>>(a);
    }

    // 3) V transpose (per batch), fp16 -> fp16
    cvt_tr_half_kernel<<<dim3(DINNER / 32, S_ / 32, B_), dim3(32, 8)>>>(
        qkvh + 2 * DINNER, vt, N1, S_,
        (long long)S_ * N1, (long long)DINNER * S_);

    // 4) sim = scale * Q K^T (causal blocks only), fp32
    {
        GemmArgs a = { qkvh, qkvh + DINNER, simP, nullptr, nullptr,
                       DINNER, N1, N1, S_,
                       (long long)S_ * N1, (long long)S_ * N1, (long long)S_ * S_,
                       scale, 1, 0 };
        gemm_mma_kernel<<<dim3(S_ / BN, S_ / BM, B_), NTH, SMEM_TOTAL>>>(a);
    }

    // 5) softmax -> fp16 probs
    softmax_kernel<<<dim3(S_, B_), 256>>>(simP, attn);

    // 6) inner = attn @ V -> fp16 only (causal K-limit)
    {
        GemmArgs a = { attn, vt, nullptr, inner, nullptr,
                       S_, S_, S_, DINNER,
                       (long long)S_ * S_, (long long)DINNER * S_,
                       (long long)S_ * DINNER,
                       1.0f, 0, 1 };
        gemm_mma_kernel<<<dim3(DINNER / BN, S_ / BM, B_), NTH, SMEM_TOTAL>>>(a);
    }

    // 7) out = inner @ W_out + b_out (fp32)
    {
        GemmArgs a = { inner, wot, out, nullptr, b_out,
                       DINNER, DINNER, DINNER, DOUT, 0, 0, 0, 1.0f, 0, 0 };
        gemm_mma_kernel<<<dim3(DOUT / BN, M1 / BM, 1), NTH, SMEM_TOTAL>>>(a);
    }
}

// round 16
// speedup vs baseline: 1.0304x; 1.0304x over previous
#include <cuda_runtime.h>
#include <cuda_fp16.h>
#include <cstdint>
#include <float.h>

// ---------------------------------------------------------------------------
// Problem constants
// ---------------------------------------------------------------------------
#define B_     4
#define S_     2048
#define DIN    1024
#define DINNER 1024
#define DOUT   1024
#define M1     (B_ * S_)        // 8192
#define N1     (3 * DINNER)     // 3072

// GEMM tile config (mma.sync)
#define BM 128
#define BN 128
#define BK 64
#define NTH 256                 // 8 warps: 4 (m) x 2 (n)
#define PAD 8
#define LDSROW (BK + PAD)       // 72 fp16 per smem row (144 B)
#define TILE_B (BM * LDSROW * 2)    // 18432 bytes per tile
#define STAGE_B (2 * TILE_B)        // A, B = 36864
#define NSTAGE 3
#define SMEM_TOTAL (NSTAGE * STAGE_B)   // 110592 (108 KB) -> 2 CTAs/SM

// ---------------------------------------------------------------------------
// PTX helpers (baseline-PTX legal on compute_103)
// ---------------------------------------------------------------------------
__device__ __forceinline__ uint32_t smem_u32(const void* p) {
    uint32_t a;
    asm("{ .reg .u64 t; cvta.to.shared.u64 t, %1; cvt.u32.u64 %0, t; }"
        : "=r"(a) : "l"(p));
    return a;
}

__device__ __forceinline__ void cp_async16(uint32_t dst, const void* src) {
    asm volatile("cp.async.cg.shared.global [%0], [%1], 16;"
                 :: "r"(dst), "l"(src));
}
#define CP_COMMIT() asm volatile("cp.async.commit_group;" ::: "memory")
#define CP_WAIT(n)  asm volatile("cp.async.wait_group %0;" :: "n"(n) : "memory")

__device__ __forceinline__ void ldmat_x4(uint32_t& r0, uint32_t& r1,
                                         uint32_t& r2, uint32_t& r3,
                                         uint32_t addr) {
    asm volatile("ldmatrix.sync.aligned.m8n8.x4.shared.b16 {%0,%1,%2,%3}, [%4];"
                 : "=r"(r0), "=r"(r1), "=r"(r2), "=r"(r3) : "r"(addr));
}

__device__ __forceinline__ void mma_fp16(float* c, const uint32_t* a,
                                         uint32_t b0, uint32_t b1) {
    asm volatile(
        "mma.sync.aligned.m16n8k16.row.col.f32.f16.f16.f32 "
        "{%0,%1,%2,%3}, {%4,%5,%6,%7}, {%8,%9}, {%0,%1,%2,%3};"
        : "+f"(c[0]), "+f"(c[1]), "+f"(c[2]), "+f"(c[3])
        : "r"(a[0]), "r"(a[1]), "r"(a[2]), "r"(a[3]), "r"(b0), "r"(b1));
}

// ---------------------------------------------------------------------------
// Scratch (static device globals)
// ---------------------------------------------------------------------------
__device__ float g_sim[(size_t)B_ * S_ * S_];            // 64 MB fp32

__device__ __half g_xh[(size_t)M1 * DIN];                // 16 MB
__device__ __half g_wqkvt[(size_t)N1 * DIN];             // 6 MB (transposed)
__device__ __half g_woutt[(size_t)DOUT * DINNER];        // 2 MB (transposed)
__device__ __half g_qkvh[(size_t)M1 * N1];               // 48 MB
__device__ __half g_vt[(size_t)B_ * DINNER * S_];        // 16 MB (V^T per batch)
__device__ __half g_attn[(size_t)B_ * S_ * S_];          // 32 MB
__device__ __half g_inner[(size_t)M1 * DINNER];          // 16 MB

// ---------------------------------------------------------------------------
// Conversion kernels
// ---------------------------------------------------------------------------
__global__ void cvt_rm_kernel(const float4* __restrict__ src,
                              __half2* __restrict__ h, long long n4) {
    long long i = (long long)blockIdx.x * blockDim.x + threadIdx.x;
    long long stride = (long long)gridDim.x * blockDim.x;
    for (; i < n4; i += stride) {
        float4 v = src[i];
        h[2 * i]     = __floats2half2_rn(v.x, v.y);
        h[2 * i + 1] = __floats2half2_rn(v.z, v.w);
    }
}

// fp32 [R,C] (row stride sld) -> transposed fp16 [C,R] (row stride dld)
__global__ void cvt_tr_kernel(const float* __restrict__ src,
                              __half* __restrict__ h,
                              int sld, int dld,
                              long long sbatch, long long dbatch) {
    __shared__ float t[32][33];
    const int c0 = blockIdx.x * 32;
    const int r0 = blockIdx.y * 32;
    const long long sb = (long long)blockIdx.z * sbatch;
    const long long db = (long long)blockIdx.z * dbatch;
    const int tx = threadIdx.x, ty = threadIdx.y;

    #pragma unroll
    for (int i = 0; i < 32; i += 8)
        t[ty + i][tx] = src[sb + (long long)(r0 + ty + i) * sld + c0 + tx];
    __syncthreads();
    #pragma unroll
    for (int i = 0; i < 32; i += 8) {
        long long o = db + (long long)(c0 + ty + i) * dld + r0 + tx;
        h[o] = __float2half(t[tx][ty + i]);
    }
}

// fp16 [R,C] (row stride sld) -> transposed fp16 [C,R] (row stride dld)
__global__ void cvt_tr_half_kernel(const __half* __restrict__ src,
                                   __half* __restrict__ h,
                                   int sld, int dld,
                                   long long sbatch, long long dbatch) {
    __shared__ __half t[32][33];
    const int c0 = blockIdx.x * 32;
    const int r0 = blockIdx.y * 32;
    const long long sb = (long long)blockIdx.z * sbatch;
    const long long db = (long long)blockIdx.z * dbatch;
    const int tx = threadIdx.x, ty = threadIdx.y;

    #pragma unroll
    for (int i = 0; i < 32; i += 8)
        t[ty + i][tx] = src[sb + (long long)(r0 + ty + i) * sld + c0 + tx];
    __syncthreads();
    #pragma unroll
    for (int i = 0; i < 32; i += 8) {
        long long o = db + (long long)(c0 + ty + i) * dld + r0 + tx;
        h[o] = t[tx][ty + i];
    }
}

// ---------------------------------------------------------------------------
// mma.sync fp16 GEMM: C[M,N] = scale * sum_k A[m,k]*B[n,k] (+bias)
// A: [M,K] K-contiguous ; B: [N,K] K-contiguous
// BK=64, 3-stage cp.async ring, 1 barrier/chunk, software-pipelined fragments,
// prefetch cp.asyncs spread across the 8 MMA phases. (R12 engine, unchanged.)
// kmax_mode additionally REVERSES the by mapping (LPT: long CTAs start first).
// ---------------------------------------------------------------------------
struct GemmArgs {
    const __half *A, *B;
    float* C;                    // nullable fp32 out
    __half* Ch;                  // nullable fp16 out
    const float* bias;           // nullable
    int K, lda, ldb, ldc;
    long long strideA, strideB, strideC;
    float scale;
    int causal_skip;             // skip CTA if bx > by
    int kmax_mode;               // K_eff = min(K, (bye+1)*128); bye reversed
};

__device__ __forceinline__ void load_tile(const __half* __restrict__ g,
                                          int row0, int ld, int k0, uint32_t sm) {
    const int tid = threadIdx.x;
    #pragma unroll
    for (int t = 0; t < 4; t++) {
        int idx = t * NTH + tid;        // 0..1023
        int r  = idx >> 3;              // 0..127
        int kc = (idx & 7) * 8;         // 0..56
        cp_async16(sm + (uint32_t)(r * LDSROW + kc) * 2,
                   g + (long long)(row0 + r) * ld + k0 + kc);
    }
}

// one 1/8 slice of a chunk prefetch: ph 0..3 -> A slice, ph 4..7 -> B slice
__device__ __forceinline__ void load_slice(const __half* __restrict__ A,
                                           const __half* __restrict__ B,
                                           int arow, int brow, int lda, int ldb,
                                           int k0, uint32_t sq, int ph, int tid) {
    if (ph < 4) {
        int idx = ph * NTH + tid;
        int r  = idx >> 3;
        int kc = (idx & 7) * 8;
        cp_async16(sq + (uint32_t)(r * LDSROW + kc) * 2,
                   A + (long long)(arow + r) * lda + k0 + kc);
    } else {
        int idx = (ph - 4) * NTH + tid;
        int r  = idx >> 3;
        int kc = (idx & 7) * 8;
        cp_async16(sq + TILE_B + (uint32_t)(r * LDSROW + kc) * 2,
                   B + (long long)(brow + r) * ldb + k0 + kc);
    }
}

__global__ void __launch_bounds__(NTH, 2)
gemm_mma_kernel(GemmArgs args)
{
    const int bx = blockIdx.x, by = blockIdx.y, bb = blockIdx.z;
    if (args.causal_skip && bx > by) return;

    // LPT reversal for causal-K-limit GEMM: longest CTAs scheduled first
    const int bye = args.kmax_mode ? ((int)gridDim.y - 1 - by) : by;

    extern __shared__ char smem[];
    const uint32_t smem_base = smem_u32(smem);

    const int tid = threadIdx.x;
    const int wid = tid >> 5;
    const int lane = tid & 31;
    const int wm = wid >> 1;            // 0..3  (32-row slab)
    const int wn = wid & 1;             // 0..1  (64-col slab)
    const int lrow = lane & 15;         // ldmatrix row select
    const int lcol = (lane >> 4) * 8;   // ldmatrix k-half select

    const __half* A = args.A + (long long)bb * args.strideA;
    const __half* B = args.B + (long long)bb * args.strideB;

    const int Keff = args.kmax_mode ? min(args.K, (bye + 1) * BM) : args.K;
    const int nch = Keff / BK;
    const int arow = bye * BM;
    const int brow = bx * BN;

    float acc[2][8][4];
    #pragma unroll
    for (int i = 0; i < 2; i++)
        #pragma unroll
        for (int j = 0; j < 8; j++)
            #pragma unroll
            for (int k = 0; k < 4; k++) acc[i][j][k] = 0.f;

    // prologue: chunks 0,1 -> stages 0,1
    load_tile(A, arow, args.lda, 0, smem_base);
    load_tile(B, brow, args.ldb, 0, smem_base + TILE_B);
    CP_COMMIT();
    if (nch > 1) {
        load_tile(A, arow, args.lda, BK, smem_base + STAGE_B);
        load_tile(B, brow, args.ldb, BK, smem_base + STAGE_B + TILE_B);
        CP_COMMIT();
    }

    // per-warp base offsets (loop-invariant)
    const uint32_t a_off0 = (uint32_t)((wm * 32 + lrow) * LDSROW) * 2 + lcol * 2;
    const uint32_t b_off0 = (uint32_t)((wn * 64 + lrow) * LDSROW) * 2 + lcol * 2;

    for (int c = 0; c < nch; c++) {
        // chunk c resident (1 group may stay in flight mid-stream)
        if (c < nch - 1) { CP_WAIT(1); } else { CP_WAIT(0); }
        __syncthreads();     // publish chunk c; stage (c+2)%3 free for overwrite

        const bool pf = (c + 2 < nch);
        const uint32_t sqpf = smem_base + ((c + 2) % NSTAGE) * STAGE_B;
        const int k0pf = (c + 2) * BK;

        const uint32_t sp = smem_base + (c % NSTAGE) * STAGE_B;
        const uint32_t a_base = sp + a_off0;
        const uint32_t b_base = sp + TILE_B + b_off0;

        // ---- software-pipelined 8 phases: (kk 0..3) x (jg 0..1) ----
        uint32_t Abuf[2][8];   // [buf][mi*4 + r]
        uint32_t Bbuf[2][8];   // [buf][b0 x4, b1 x4]

        // preload phase 0 fragments: A(kk=0), B(kk=0, jg=0)
        {
            ldmat_x4(Abuf[0][0], Abuf[0][1], Abuf[0][2], Abuf[0][3], a_base);
            ldmat_x4(Abuf[0][4], Abuf[0][5], Abuf[0][6], Abuf[0][7],
                     a_base + (uint32_t)(16 * LDSROW) * 2);
            #pragma unroll
            for (int np = 0; np < 2; np++) {
                uint32_t r0, r1, r2, r3;
                ldmat_x4(r0, r1, r2, r3,
                         b_base + (uint32_t)(np * 16 * LDSROW) * 2);
                Bbuf[0][np * 2]     = r0; Bbuf[0][4 + np * 2]     = r2;
                Bbuf[0][np * 2 + 1] = r1; Bbuf[0][4 + np * 2 + 1] = r3;
            }
        }

        #pragma unroll
        for (int ph = 0; ph < 8; ph++) {
            const int jg = ph & 1;
            const int kk = ph >> 1;
            const int ab = kk & 1;
            const int bbuf = ph & 1;

            // one slice of the chunk-(c+2) gmem prefetch per phase
            if (pf)
                load_slice(A, B, arow, brow, args.lda, args.ldb,
                           k0pf, sqpf, ph, tid);

            // prefetch next phase's fragments
            if (ph < 7) {
                const int nkk = (ph + 1) >> 1;
                const int njg = (ph + 1) & 1;
                const uint32_t nkoff = (uint32_t)(nkk * 16) * 2;
                if (njg == 0) {   // new kk: load A(nkk)
                    const int nab = nkk & 1;
                    ldmat_x4(Abuf[nab][0], Abuf[nab][1], Abuf[nab][2], Abuf[nab][3],
                             a_base + nkoff);
                    ldmat_x4(Abuf[nab][4], Abuf[nab][5], Abuf[nab][6], Abuf[nab][7],
                             a_base + (uint32_t)(16 * LDSROW) * 2 + nkoff);
                }
                const int nbb = (ph + 1) & 1;
                #pragma unroll
                for (int np = 0; np < 2; np++) {
                    uint32_t r0, r1, r2, r3;
                    ldmat_x4(r0, r1, r2, r3,
                             b_base + (uint32_t)((njg * 2 + np) * 16 * LDSROW) * 2
                                    + nkoff);
                    Bbuf[nbb][np * 2]     = r0; Bbuf[nbb][4 + np * 2]     = r2;
                    Bbuf[nbb][np * 2 + 1] = r1; Bbuf[nbb][4 + np * 2 + 1] = r3;
                }
            }

            // 8 MMAs for this phase
            #pragma unroll
            for (int mi = 0; mi < 2; mi++)
                #pragma unroll
                for (int jl = 0; jl < 4; jl++)
                    mma_fp16(acc[mi][jg * 4 + jl], &Abuf[ab][mi * 4],
                             Bbuf[bbuf][jl], Bbuf[bbuf][4 + jl]);
        }

        if (pf) CP_COMMIT();
    }

    // epilogue (acc is thread-private; no sync needed)
    float* C = args.C ? args.C + (long long)bb * args.strideC : nullptr;
    __half* Ch = args.Ch ? args.Ch + (long long)bb * args.strideC : nullptr;
    const int g = lane >> 2;
    const int tig = lane & 3;

    #pragma unroll
    for (int mi = 0; mi < 2; mi++) {
        #pragma unroll
        for (int j = 0; j < 8; j++) {
            const int row0 = arow + wm * 32 + mi * 16 + g;
            const int col0 = brow + wn * 64 + j * 8 + 2 * tig;
            float v[4];
            #pragma unroll
            for (int k = 0; k < 4; k++) v[k] = acc[mi][j][k] * args.scale;
            if (args.bias) {
                v[0] += args.bias[col0];     v[1] += args.bias[col0 + 1];
                v[2] += args.bias[col0];     v[3] += args.bias[col0 + 1];
            }
            const long long o0 = (long long)row0 * args.ldc + col0;
            const long long o1 = (long long)(row0 + 8) * args.ldc + col0;
            if (C) {
                C[o0] = v[0]; C[o0 + 1] = v[1];
                C[o1] = v[2]; C[o1 + 1] = v[3];
            }
            if (Ch) {
                *(__half2*)(Ch + o0) = __floats2half2_rn(v[0], v[1]);
                *(__half2*)(Ch + o1) = __floats2half2_rn(v[2], v[3]);
            }
        }
    }
}

// ---------------------------------------------------------------------------
// Causal row softmax: fp32 sim -> fp16 probs.
// SINGLE gmem read pass: row cached in 8 regs/thread (max 2048 = 8*256).
// ---------------------------------------------------------------------------
__global__ void __launch_bounds__(256)
softmax_kernel(const float* __restrict__ sim, __half* __restrict__ ph)
{
    const int i = blockIdx.x;
    const int b = blockIdx.y;
    const float* row = sim + ((size_t)b * S_ + i) * S_;
    __half* rh = ph + ((size_t)b * S_ + i) * S_;
    const int n = i + 1;

    __shared__ float red[256];
    const int t = threadIdx.x;

    // pass 1: load row into registers, compute max
    float v[8];
    float m = -FLT_MAX;
    #pragma unroll
    for (int it = 0; it < 8; it++) {
        int j = t + it * 256;
        v[it] = (j < n) ? row[j] : -FLT_MAX;
        m = fmaxf(m, v[it]);
    }
    red[t] = m; __syncthreads();
    for (int s = 128; s > 0; s >>= 1) {
        if (t < s) red[t] = fmaxf(red[t], red[t + s]);
        __syncthreads();
    }
    m = red[0]; __syncthreads();

    // pass 2 (registers only): exp + sum
    float sum = 0.f;
    #pragma unroll
    for (int it = 0; it < 8; it++) {
        int j = t + it * 256;
        float e = (j < n) ? expf(v[it] - m) : 0.f;
        v[it] = e;
        sum += e;
    }
    red[t] = sum; __syncthreads();
    for (int s = 128; s > 0; s >>= 1) {
        if (t < s) red[t] += red[t + s];
        __syncthreads();
    }
    const float inv = 1.f / red[0];

    // write fp16 probs
    #pragma unroll
    for (int it = 0; it < 8; it++) {
        int j = t + it * 256;
        if (j < n) rh[j] = __float2half(v[it] * inv);
    }
    // zero-fill to end of 128-block (PV reads whole tiles)
    const int pad_end = min(S_, ((n + 127) / 128) * 128);
    for (int j = n + t; j < pad_end; j += 256)
        rh[j] = __float2half(0.f);
}

// ---------------------------------------------------------------------------
// Launch
// ---------------------------------------------------------------------------
static void* sym(const void* s) { void* p; cudaGetSymbolAddress(&p, s); return p; }

extern "C" void kernel_launch(void* const* d_in, const int* in_sizes, int n_in,
                              void* d_out, int out_size)
{
    const float* x     = (const float*)d_in[0];
    const float* w_qkv = (const float*)d_in[1];
    const float* w_out = (const float*)d_in[2];
    const float* b_out = (const float*)d_in[3];
    float* out = (float*)d_out;

    float* simP = (float*)sym(g_sim);
    __half* xh    = (__half*)sym(g_xh);
    __half* wqt   = (__half*)sym(g_wqkvt);
    __half* wot   = (__half*)sym(g_woutt);
    __half* qkvh  = (__half*)sym(g_qkvh);
    __half* vt    = (__half*)sym(g_vt);
    __half* attn  = (__half*)sym(g_attn);
    __half* inner = (__half*)sym(g_inner);

    cudaFuncSetAttribute(gemm_mma_kernel,
                         cudaFuncAttributeMaxDynamicSharedMemorySize, SMEM_TOTAL);

    const float scale = 1.0f / 32.0f;   // DIM_INNER^-0.5

    // 1) input conversion / weight transposes
    cvt_rm_kernel<<<2048, 256>>>((const float4*)x, (__half2*)xh,
                                 (long long)M1 * DIN / 4);
    cvt_tr_kernel<<<dim3(N1 / 32, DIN / 32, 1), dim3(32, 8)>>>(
        w_qkv, wqt, N1, DIN, 0, 0);
    cvt_tr_kernel<<<dim3(DOUT / 32, DINNER / 32, 1), dim3(32, 8)>>>(
        w_out, wot, DOUT, DINNER, 0, 0);

    // 2) QKV projection -> fp16 qkvh only
    {
        GemmArgs a = { xh, wqt, nullptr, qkvh, nullptr,
                       DIN, DIN, DIN, N1, 0, 0, 0, 1.0f, 0, 0 };
        gemm_mma_kernel<<<dim3(N1 / BN, M1 / BM, 1), NTH, SMEM_TOTAL>>>(a);
    }

    // 3) V transpose (per batch), fp16 -> fp16
    cvt_tr_half_kernel<<<dim3(DINNER / 32, S_ / 32, B_), dim3(32, 8)>>>(
        qkvh + 2 * DINNER, vt, N1, S_,
        (long long)S_ * N1, (long long)DINNER * S_);

    // 4) sim = scale * Q K^T (causal blocks only), fp32
    {
        GemmArgs a = { qkvh, qkvh + DINNER, simP, nullptr, nullptr,
                       DINNER, N1, N1, S_,
                       (long long)S_ * N1, (long long)S_ * N1, (long long)S_ * S_,
                       scale, 1, 0 };
        gemm_mma_kernel<<<dim3(S_ / BN, S_ / BM, B_), NTH, SMEM_TOTAL>>>(a);
    }

    // 5) softmax -> fp16 probs (single-read-pass)
    softmax_kernel<<<dim3(S_, B_), 256>>>(simP, attn);

    // 6) inner = attn @ V -> fp16 only (causal K-limit, LPT-reversed by)
    {
        GemmArgs a = { attn, vt, nullptr, inner, nullptr,
                       S_, S_, S_, DINNER,
                       (long long)S_ * S_, (long long)DINNER * S_,
                       (long long)S_ * DINNER,
                       1.0f, 0, 1 };
        gemm_mma_kernel<<<dim3(DINNER / BN, S_ / BM, B_), NTH, SMEM_TOTAL>>>(a);
    }

    // 7) out = inner @ W_out + b_out (fp32)
    {
        GemmArgs a = { inner, wot, out, nullptr, b_out,
                       DINNER, DINNER, DINNER, DOUT, 0, 0, 0, 1.0f, 0, 0 };
        gemm_mma_kernel<<<dim3(DOUT / BN, M1 / BM, 1), NTH, SMEM_TOTAL>>>(a);
    }
}